// round 1
// baseline (speedup 1.0000x reference)
#include <cuda_runtime.h>

// Problem constants (fixed by the reference)
constexpr int B_  = 4;
constexpr int S_  = 2048;
constexpr int DIN = 1024;
constexpr int DOUT = 1024;
constexpr int H_  = 16;
constexpr int HD_ = 64;
constexpr int M_  = B_ * S_;   // 8192 rows

// Scratch (device globals: allocation-free contract)
__device__ float g_q[(size_t)M_ * DOUT];    // [B,H,S,HD]
__device__ float g_k[(size_t)M_ * DOUT];    // [B,H,S,HD]
__device__ float g_v[(size_t)M_ * DOUT];    // [B,H,S,HD]
__device__ float g_ctx[(size_t)M_ * DOUT];  // [B,S,H*HD] row-major

// ---------------------------------------------------------------------------
// GEMM: C = A[M,K] * W[N,K]^T   (both row-major, K contiguous -> NT gemm)
// Block tile 128x128, BK=8, 256 threads, 8x8 per thread.
// QKV_LAYOUT: write C[m,n] to [B,H,S,HD] layout; else row-major [M,N] (+bias).
// ---------------------------------------------------------------------------
template <bool QKV_LAYOUT, bool ADD_BIAS>
__global__ __launch_bounds__(256)
void gemm_nt_kernel(const float* __restrict__ A, const float* __restrict__ W,
                    const float* __restrict__ bias, float* __restrict__ C)
{
    constexpr int K  = 1024;
    constexpr int BM = 128, BK = 8;

    __shared__ float As[BK][BM];
    __shared__ float Bs[BK][BM];

    const int t  = threadIdx.x;
    const int bm = blockIdx.y * 128;
    const int bn = blockIdx.x * 128;

    const int lr = t >> 1;          // 0..127: row of A/W tile this thread loads
    const int lc = (t & 1) << 2;    // k offset 0 or 4

    const int tx = t & 15;          // 0..15 -> output cols tx*4 (+64)
    const int ty = t >> 4;          // 0..15 -> output rows ty*4 (+64)

    const float* Ap = A + (size_t)(bm + lr) * K + lc;
    const float* Wp = W + (size_t)(bn + lr) * K + lc;

    float acc[8][8];
#pragma unroll
    for (int i = 0; i < 8; i++)
#pragma unroll
        for (int j = 0; j < 8; j++) acc[i][j] = 0.f;

    for (int k0 = 0; k0 < K; k0 += BK) {
        const float4 av = *(const float4*)(Ap + k0);
        const float4 wv = *(const float4*)(Wp + k0);
        __syncthreads();   // previous iteration's compute done before overwrite
        As[lc + 0][lr] = av.x; As[lc + 1][lr] = av.y;
        As[lc + 2][lr] = av.z; As[lc + 3][lr] = av.w;
        Bs[lc + 0][lr] = wv.x; Bs[lc + 1][lr] = wv.y;
        Bs[lc + 2][lr] = wv.z; Bs[lc + 3][lr] = wv.w;
        __syncthreads();
#pragma unroll
        for (int kk = 0; kk < BK; kk++) {
            float ar[8], br[8];
            *(float4*)&ar[0] = *(const float4*)&As[kk][ty * 4];
            *(float4*)&ar[4] = *(const float4*)&As[kk][64 + ty * 4];
            *(float4*)&br[0] = *(const float4*)&Bs[kk][tx * 4];
            *(float4*)&br[4] = *(const float4*)&Bs[kk][64 + tx * 4];
#pragma unroll
            for (int i = 0; i < 8; i++)
#pragma unroll
                for (int j = 0; j < 8; j++)
                    acc[i][j] = fmaf(ar[i], br[j], acc[i][j]);
        }
    }

#pragma unroll
    for (int i = 0; i < 8; i++) {
        const int m = bm + ((i < 4) ? (ty * 4 + i) : (64 + ty * 4 + (i - 4)));
#pragma unroll
        for (int jj = 0; jj < 2; jj++) {
            const int n = bn + jj * 64 + tx * 4;
            float4 v;
            v.x = acc[i][jj * 4 + 0]; v.y = acc[i][jj * 4 + 1];
            v.z = acc[i][jj * 4 + 2]; v.w = acc[i][jj * 4 + 3];
            if (ADD_BIAS) {
                const float4 bv = *(const float4*)(bias + n);
                v.x += bv.x; v.y += bv.y; v.z += bv.z; v.w += bv.w;
            }
            size_t idx;
            if (QKV_LAYOUT) {
                const int b = m >> 11, s = m & 2047;
                const int h = n >> 6,  hd = n & 63;
                idx = (((size_t)(b * H_ + h) * S_ + s) << 6) + hd;
            } else {
                idx = (size_t)m * DOUT + n;
            }
            *(float4*)(C + idx) = v;
        }
    }
}

// ---------------------------------------------------------------------------
// Causal flash attention, fp32. One block per (b*h, 64-row q tile).
// 256 threads. smem: qs (q*scale), b1 (K swizzled, then V linear), b2 (P).
// Thread (ty,tx): ty=rows 4ty..4ty+3, tx=cols 4tx..4tx+3 (scores and PV).
// ---------------------------------------------------------------------------
__global__ __launch_bounds__(256)
void attn_kernel(const float* __restrict__ Q, const float* __restrict__ Kg,
                 const float* __restrict__ Vg, float* __restrict__ ctx)
{
    __shared__ float qs[64][64];
    __shared__ float b1[64][64];   // K (xor-swizzled) then V (linear)
    __shared__ float b2[64][64];   // P

    const int t  = threadIdx.x;
    const int tx = t & 15;
    const int ty = t >> 4;
    const int bh = blockIdx.x;                                   // b*16 + h
    const int qt = (int)gridDim.y - 1 - (int)blockIdx.y;         // long blocks first
    const int q0 = qt * 64;

    const float* Qb = Q  + (size_t)bh * S_ * HD_;
    const float* Kb = Kg + (size_t)bh * S_ * HD_;
    const float* Vb = Vg + (size_t)bh * S_ * HD_;

    // Load q tile, pre-scaled by 1/sqrt(HD)=0.125
#pragma unroll
    for (int it = 0; it < 4; it++) {
        const int i = t + it * 256;            // 0..1023 float4 units
        const int r = i >> 4, c4 = (i & 15) << 2;
        float4 v = *(const float4*)(Qb + (size_t)(q0 + r) * HD_ + c4);
        v.x *= 0.125f; v.y *= 0.125f; v.z *= 0.125f; v.w *= 0.125f;
        *(float4*)&qs[r][c4] = v;
    }

    float m[4], l[4], acc[4][4];
#pragma unroll
    for (int i = 0; i < 4; i++) {
        m[i] = -1e30f; l[i] = 0.f;
#pragma unroll
        for (int j = 0; j < 4; j++) acc[i][j] = 0.f;
    }

    for (int kt = 0; kt <= qt; kt++) {
        const int k0 = kt * 64;

        __syncthreads();   // previous tile's PV done with b1/b2
        // Load K tile, xor-swizzled columns: element K[k0+r][c] -> b1[r][c ^ (r&28)]
#pragma unroll
        for (int it = 0; it < 4; it++) {
            const int i = t + it * 256;
            const int r = i >> 4, c4 = (i & 15) << 2;
            *(float4*)&b1[r][c4 ^ (r & 28)] =
                *(const float4*)(Kb + (size_t)(k0 + r) * HD_ + c4);
        }
        __syncthreads();

        // --- scores: s[i][j] = (q*scale) . k  over d=0..63 ---
        float s[4][4];
#pragma unroll
        for (int i = 0; i < 4; i++)
#pragma unroll
            for (int j = 0; j < 4; j++) s[i][j] = 0.f;

#pragma unroll 8
        for (int d = 0; d < 64; d++) {
            float qv[4], kv[4];
#pragma unroll
            for (int i = 0; i < 4; i++) qv[i] = qs[ty * 4 + i][d];
#pragma unroll
            for (int j = 0; j < 4; j++) {
                const int kc = tx * 4 + j;
                kv[j] = b1[kc][d ^ (kc & 28)];
            }
#pragma unroll
            for (int i = 0; i < 4; i++)
#pragma unroll
                for (int j = 0; j < 4; j++)
                    s[i][j] = fmaf(qv[i], kv[j], s[i][j]);
        }

        // causal mask (only the diagonal tile needs it)
        if (kt == qt) {
#pragma unroll
            for (int i = 0; i < 4; i++)
#pragma unroll
                for (int j = 0; j < 4; j++)
                    if ((k0 + tx * 4 + j) > (q0 + ty * 4 + i)) s[i][j] = -1e30f;
        }

        // --- online softmax (row stats replicated across the 16 tx threads) ---
        float alpha[4];
#pragma unroll
        for (int i = 0; i < 4; i++) {
            float rm = fmaxf(fmaxf(s[i][0], s[i][1]), fmaxf(s[i][2], s[i][3]));
            rm = fmaxf(rm, __shfl_xor_sync(0xffffffffu, rm, 8, 16));
            rm = fmaxf(rm, __shfl_xor_sync(0xffffffffu, rm, 4, 16));
            rm = fmaxf(rm, __shfl_xor_sync(0xffffffffu, rm, 2, 16));
            rm = fmaxf(rm, __shfl_xor_sync(0xffffffffu, rm, 1, 16));
            const float mnew = fmaxf(m[i], rm);
            alpha[i] = __expf(m[i] - mnew);
            float rs = 0.f;
#pragma unroll
            for (int j = 0; j < 4; j++) {
                const float p = __expf(s[i][j] - mnew);
                s[i][j] = p;
                rs += p;
            }
            rs += __shfl_xor_sync(0xffffffffu, rs, 8, 16);
            rs += __shfl_xor_sync(0xffffffffu, rs, 4, 16);
            rs += __shfl_xor_sync(0xffffffffu, rs, 2, 16);
            rs += __shfl_xor_sync(0xffffffffu, rs, 1, 16);
            l[i] = l[i] * alpha[i] + rs;
            m[i] = mnew;
        }

        __syncthreads();   // all warps done reading b1 as K

        // write P to b2; load V tile into b1 (linear layout)
#pragma unroll
        for (int i = 0; i < 4; i++)
#pragma unroll
            for (int j = 0; j < 4; j++)
                b2[ty * 4 + i][tx * 4 + j] = s[i][j];
#pragma unroll
        for (int it = 0; it < 4; it++) {
            const int i = t + it * 256;
            const int r = i >> 4, c4 = (i & 15) << 2;
            *(float4*)&b1[r][c4] = *(const float4*)(Vb + (size_t)(k0 + r) * HD_ + c4);
        }
        __syncthreads();

        // --- PV: acc[i][j] = acc*alpha + sum_kc P[row][kc] * V[kc][dcol] ---
#pragma unroll
        for (int i = 0; i < 4; i++)
#pragma unroll
            for (int j = 0; j < 4; j++) acc[i][j] *= alpha[i];

#pragma unroll 8
        for (int kc = 0; kc < 64; kc++) {
            float pv[4], vv[4];
#pragma unroll
            for (int i = 0; i < 4; i++) pv[i] = b2[ty * 4 + i][kc];
#pragma unroll
            for (int j = 0; j < 4; j++) vv[j] = b1[kc][tx * 4 + j];
#pragma unroll
            for (int i = 0; i < 4; i++)
#pragma unroll
                for (int j = 0; j < 4; j++)
                    acc[i][j] = fmaf(pv[i], vv[j], acc[i][j]);
        }
    }

    // Write ctx in [B, S, H*HD] row-major
    const int b = bh >> 4, h = bh & 15;
#pragma unroll
    for (int i = 0; i < 4; i++) {
        const float inv = 1.f / l[i];
        float4 v;
        v.x = acc[i][0] * inv; v.y = acc[i][1] * inv;
        v.z = acc[i][2] * inv; v.w = acc[i][3] * inv;
        const size_t row = (size_t)(b * S_ + q0 + ty * 4 + i);
        *(float4*)(ctx + row * DOUT + h * HD_ + tx * 4) = v;
    }
}

// ---------------------------------------------------------------------------
extern "C" void kernel_launch(void* const* d_in, const int* in_sizes, int n_in,
                              void* d_out, int out_size)
{
    (void)in_sizes; (void)n_in; (void)out_size;

    const float* x  = (const float*)d_in[0];
    const float* Wq = (const float*)d_in[1];
    const float* Wk = (const float*)d_in[2];
    const float* Wv = (const float*)d_in[3];
    const float* Wo = (const float*)d_in[4];
    const float* bo = (const float*)d_in[5];
    float* out = (float*)d_out;

    float *q, *k, *v, *c;
    cudaGetSymbolAddress((void**)&q, g_q);
    cudaGetSymbolAddress((void**)&k, g_k);
    cudaGetSymbolAddress((void**)&v, g_v);
    cudaGetSymbolAddress((void**)&c, g_ctx);

    const dim3 gemm_grid(DOUT / 128, M_ / 128);   // (8, 64)
    gemm_nt_kernel<true,  false><<<gemm_grid, 256>>>(x, Wq, nullptr, q);
    gemm_nt_kernel<true,  false><<<gemm_grid, 256>>>(x, Wk, nullptr, k);
    gemm_nt_kernel<true,  false><<<gemm_grid, 256>>>(x, Wv, nullptr, v);

    attn_kernel<<<dim3(B_ * H_, S_ / 64), 256>>>(q, k, v, c);

    gemm_nt_kernel<false, true ><<<gemm_grid, 256>>>(c, Wo, bo, out);
}

// round 3
// speedup vs baseline: 1.6788x; 1.6788x over previous
#include <cuda_runtime.h>
#include <cuda_bf16.h>
#include <cstdint>

// Problem constants
constexpr int B_   = 4;
constexpr int S_   = 2048;
constexpr int DIN  = 1024;
constexpr int DOUT = 1024;
constexpr int H_   = 16;
constexpr int HD_  = 64;
constexpr int M_   = B_ * S_;   // 8192
constexpr int K_   = 1024;

// ---------------- scratch (device globals; allocation-free contract) --------
__device__ float g_q[(size_t)M_ * DOUT];
__device__ float g_k[(size_t)M_ * DOUT];
__device__ float g_v[(size_t)M_ * DOUT];
__device__ float g_ctx[(size_t)M_ * DOUT];
__device__ __nv_bfloat16 g_xh[(size_t)M_ * DIN];
__device__ __nv_bfloat16 g_xl[(size_t)M_ * DIN];
__device__ __nv_bfloat16 g_ch[(size_t)M_ * DOUT];
__device__ __nv_bfloat16 g_cl[(size_t)M_ * DOUT];
__device__ __nv_bfloat16 g_wh[4][(size_t)DOUT * DIN];
__device__ __nv_bfloat16 g_wl[4][(size_t)DOUT * DIN];

// ---------------- helpers (sm_80-safe PTX only) -----------------------------
__device__ __forceinline__ uint32_t smem_u32(const void* p) {
    uint32_t a;
    asm("{ .reg .u64 t; cvta.to.shared.u64 t, %1; cvt.u32.u64 %0, t; }"
        : "=r"(a) : "l"(p));
    return a;
}
__device__ __forceinline__ void cp_async16(uint32_t dst, const void* src) {
    asm volatile("cp.async.cg.shared.global [%0], [%1], 16;"
                 :: "r"(dst), "l"(src) : "memory");
}
#define CP_COMMIT() asm volatile("cp.async.commit_group;" ::: "memory")
#define CP_WAIT1()  asm volatile("cp.async.wait_group 1;" ::: "memory")
#define CP_WAIT0()  asm volatile("cp.async.wait_group 0;" ::: "memory")

__device__ __forceinline__ void ldsm4(uint32_t* r, uint32_t addr) {
    asm volatile("ldmatrix.sync.aligned.m8n8.x4.shared.b16 {%0,%1,%2,%3}, [%4];"
                 : "=r"(r[0]), "=r"(r[1]), "=r"(r[2]), "=r"(r[3]) : "r"(addr));
}
__device__ __forceinline__ void mma_bf16(float* c, const uint32_t* a, const uint32_t* b) {
    asm volatile(
        "mma.sync.aligned.m16n8k16.row.col.f32.bf16.bf16.f32 "
        "{%0,%1,%2,%3}, {%4,%5,%6,%7}, {%8,%9}, {%0,%1,%2,%3};"
        : "+f"(c[0]), "+f"(c[1]), "+f"(c[2]), "+f"(c[3])
        : "r"(a[0]), "r"(a[1]), "r"(a[2]), "r"(a[3]), "r"(b[0]), "r"(b[1]));
}

// ---------------- split fp32 -> bf16 hi + bf16 lo ---------------------------
__global__ __launch_bounds__(256)
void split_kernel(const float* __restrict__ in, __nv_bfloat16* __restrict__ hi,
                  __nv_bfloat16* __restrict__ lo, int n4)
{
    int i = blockIdx.x * 256 + threadIdx.x;
    if (i >= n4) return;
    float4 v = ((const float4*)in)[i];
    __nv_bfloat16 h0 = __float2bfloat16(v.x), h1 = __float2bfloat16(v.y);
    __nv_bfloat16 h2 = __float2bfloat16(v.z), h3 = __float2bfloat16(v.w);
    __nv_bfloat16 l0 = __float2bfloat16(v.x - __bfloat162float(h0));
    __nv_bfloat16 l1 = __float2bfloat16(v.y - __bfloat162float(h1));
    __nv_bfloat16 l2 = __float2bfloat16(v.z - __bfloat162float(h2));
    __nv_bfloat16 l3 = __float2bfloat16(v.w - __bfloat162float(h3));
    __nv_bfloat162* hp = (__nv_bfloat162*)hi;
    __nv_bfloat162* lp = (__nv_bfloat162*)lo;
    hp[2 * i]     = __halves2bfloat162(h0, h1);
    hp[2 * i + 1] = __halves2bfloat162(h2, h3);
    lp[2 * i]     = __halves2bfloat162(l0, l1);
    lp[2 * i + 1] = __halves2bfloat162(l2, l3);
}

// ---------------- HMMA GEMM: C[M,N] = A[M,K] * W[N,K]^T ---------------------
// Split: C = Ah*Bh + Ah*Bl + Al*Bh (fp32 accum).
// Block 128x128, BK=64, 8 warps (warp tile 64x32, 2x4 grid), cp.async 2-stage.
// SMEM per stage: AH 16K | AL 16K | BH 16K | BL 16K = 64KB; 2 stages = 128KB.
constexpr int GEMM_SMEM = 131072;

template <bool QKV, bool BIAS>
__global__ __launch_bounds__(256, 1)
void gemm_mma(const __nv_bfloat16* __restrict__ Ah, const __nv_bfloat16* __restrict__ Al,
              const __nv_bfloat16* __restrict__ Bh, const __nv_bfloat16* __restrict__ Bl,
              const float* __restrict__ bias, float* __restrict__ C)
{
    extern __shared__ char smem[];
    const uint32_t sb = smem_u32(smem);

    const int t = threadIdx.x, lane = t & 31, wid = t >> 5;
    const int wm = wid & 1, wn = wid >> 1;          // 2 x 4 warp grid
    const int bm = blockIdx.y * 128, bn = blockIdx.x * 128;

    // async-copy one K-chunk (64 cols) of all four tiles into stage buf
    auto issue = [&](int ch, int buf) {
        const int k0 = ch * 64;
        const uint32_t st = sb + buf * 65536;
#pragma unroll
        for (int it = 0; it < 4; it++) {
            const int u = t + it * 256;             // 0..1023 -> (row, 16B-group)
            const int r = u >> 3, j = u & 7;
            const uint32_t so = (uint32_t)(r * 128 + ((j ^ (r & 7)) << 4));
            const size_t go = (size_t)r * (K_ * 2) + (size_t)k0 * 2 + (size_t)j * 16;
            cp_async16(st +         so, (const char*)Ah + (size_t)bm * (K_ * 2) + go);
            cp_async16(st + 16384 + so, (const char*)Al + (size_t)bm * (K_ * 2) + go);
            cp_async16(st + 32768 + so, (const char*)Bh + (size_t)bn * (K_ * 2) + go);
            cp_async16(st + 49152 + so, (const char*)Bl + (size_t)bn * (K_ * 2) + go);
        }
    };

    float acc[4][4][4];
#pragma unroll
    for (int mi = 0; mi < 4; mi++)
#pragma unroll
        for (int ni = 0; ni < 4; ni++)
#pragma unroll
            for (int e = 0; e < 4; e++) acc[mi][ni][e] = 0.f;

    issue(0, 0); CP_COMMIT();

    for (int ch = 0; ch < 16; ch++) {
        const int buf = ch & 1;
        if (ch + 1 < 16) { issue(ch + 1, buf ^ 1); CP_COMMIT(); CP_WAIT1(); }
        else             { CP_WAIT0(); }
        __syncthreads();

        const uint32_t st = sb + buf * 65536;
#pragma unroll
        for (int ks = 0; ks < 4; ks++) {
            // A fragments: 4 m16 tiles, hi & lo
            uint32_t ah[4][4], al[4][4];
            const int arow = wm * 64 + (lane & 15);
            const int aj   = ks * 2 + (lane >> 4);
#pragma unroll
            for (int mi = 0; mi < 4; mi++) {
                const int r = arow + mi * 16;
                const uint32_t off = (uint32_t)(r * 128 + ((aj ^ (r & 7)) << 4));
                ldsm4(ah[mi], st + off);
                ldsm4(al[mi], st + 16384 + off);
            }
            // B fragments: 4 n8 tiles, hi & lo (two x4 loads each cover 2 tiles)
            uint32_t bh[4][2], bl[4][2];
            const int t4 = lane >> 3, rr = lane & 7;
            const int bj = ks * 2 + (t4 & 1);
#pragma unroll
            for (int pi = 0; pi < 2; pi++) {
                const int n = wn * 32 + pi * 16 + ((t4 >> 1) << 3) + rr;
                const uint32_t off = (uint32_t)(n * 128 + ((bj ^ (n & 7)) << 4));
                uint32_t r4[4];
                ldsm4(r4, st + 32768 + off);
                bh[2 * pi][0] = r4[0]; bh[2 * pi][1] = r4[1];
                bh[2 * pi + 1][0] = r4[2]; bh[2 * pi + 1][1] = r4[3];
                ldsm4(r4, st + 49152 + off);
                bl[2 * pi][0] = r4[0]; bl[2 * pi][1] = r4[1];
                bl[2 * pi + 1][0] = r4[2]; bl[2 * pi + 1][1] = r4[3];
            }
#pragma unroll
            for (int mi = 0; mi < 4; mi++)
#pragma unroll
                for (int ni = 0; ni < 4; ni++) {
                    mma_bf16(acc[mi][ni], ah[mi], bh[ni]);
                    mma_bf16(acc[mi][ni], ah[mi], bl[ni]);
                    mma_bf16(acc[mi][ni], al[mi], bh[ni]);
                }
        }
        __syncthreads();
    }

    // epilogue: accum layout m16n8 -> lane (row l/4 [+8], cols 2(l%4)+{0,1})
#pragma unroll
    for (int mi = 0; mi < 4; mi++) {
#pragma unroll
        for (int ni = 0; ni < 4; ni++) {
            const int r0 = bm + wm * 64 + mi * 16 + (lane >> 2);
            const int cc = bn + wn * 32 + ni * 8 + 2 * (lane & 3);
#pragma unroll
            for (int half = 0; half < 2; half++) {
                const int r = r0 + half * 8;
                float2 v;
                v.x = acc[mi][ni][half * 2 + 0];
                v.y = acc[mi][ni][half * 2 + 1];
                if (BIAS) { v.x += bias[cc]; v.y += bias[cc + 1]; }
                size_t idx;
                if (QKV) {
                    const int b = r >> 11, s = r & 2047;
                    const int h = cc >> 6, hd = cc & 63;
                    idx = (((size_t)(b * H_ + h) * S_ + s) << 6) + hd;
                } else {
                    idx = (size_t)r * DOUT + cc;
                }
                *(float2*)(C + idx) = v;
            }
        }
    }
}

// ---------------- causal flash attention (fp32 SIMT, unchanged) -------------
__global__ __launch_bounds__(256)
void attn_kernel(const float* __restrict__ Q, const float* __restrict__ Kg,
                 const float* __restrict__ Vg, float* __restrict__ ctx)
{
    __shared__ float qs[64][64];
    __shared__ float b1[64][64];
    __shared__ float b2[64][64];

    const int t  = threadIdx.x;
    const int tx = t & 15;
    const int ty = t >> 4;
    const int bh = blockIdx.x;
    const int qt = (int)gridDim.y - 1 - (int)blockIdx.y;
    const int q0 = qt * 64;

    const float* Qb = Q  + (size_t)bh * S_ * HD_;
    const float* Kb = Kg + (size_t)bh * S_ * HD_;
    const float* Vb = Vg + (size_t)bh * S_ * HD_;

#pragma unroll
    for (int it = 0; it < 4; it++) {
        const int i = t + it * 256;
        const int r = i >> 4, c4 = (i & 15) << 2;
        float4 v = *(const float4*)(Qb + (size_t)(q0 + r) * HD_ + c4);
        v.x *= 0.125f; v.y *= 0.125f; v.z *= 0.125f; v.w *= 0.125f;
        *(float4*)&qs[r][c4] = v;
    }

    float m[4], l[4], acc[4][4];
#pragma unroll
    for (int i = 0; i < 4; i++) {
        m[i] = -1e30f; l[i] = 0.f;
#pragma unroll
        for (int j = 0; j < 4; j++) acc[i][j] = 0.f;
    }

    for (int kt = 0; kt <= qt; kt++) {
        const int k0 = kt * 64;
        __syncthreads();
#pragma unroll
        for (int it = 0; it < 4; it++) {
            const int i = t + it * 256;
            const int r = i >> 4, c4 = (i & 15) << 2;
            *(float4*)&b1[r][c4 ^ (r & 28)] =
                *(const float4*)(Kb + (size_t)(k0 + r) * HD_ + c4);
        }
        __syncthreads();

        float s[4][4];
#pragma unroll
        for (int i = 0; i < 4; i++)
#pragma unroll
            for (int j = 0; j < 4; j++) s[i][j] = 0.f;

#pragma unroll 8
        for (int d = 0; d < 64; d++) {
            float qv[4], kv[4];
#pragma unroll
            for (int i = 0; i < 4; i++) qv[i] = qs[ty * 4 + i][d];
#pragma unroll
            for (int j = 0; j < 4; j++) {
                const int kc = tx * 4 + j;
                kv[j] = b1[kc][d ^ (kc & 28)];
            }
#pragma unroll
            for (int i = 0; i < 4; i++)
#pragma unroll
                for (int j = 0; j < 4; j++)
                    s[i][j] = fmaf(qv[i], kv[j], s[i][j]);
        }

        if (kt == qt) {
#pragma unroll
            for (int i = 0; i < 4; i++)
#pragma unroll
                for (int j = 0; j < 4; j++)
                    if ((k0 + tx * 4 + j) > (q0 + ty * 4 + i)) s[i][j] = -1e30f;
        }

        float alpha[4];
#pragma unroll
        for (int i = 0; i < 4; i++) {
            float rm = fmaxf(fmaxf(s[i][0], s[i][1]), fmaxf(s[i][2], s[i][3]));
            rm = fmaxf(rm, __shfl_xor_sync(0xffffffffu, rm, 8, 16));
            rm = fmaxf(rm, __shfl_xor_sync(0xffffffffu, rm, 4, 16));
            rm = fmaxf(rm, __shfl_xor_sync(0xffffffffu, rm, 2, 16));
            rm = fmaxf(rm, __shfl_xor_sync(0xffffffffu, rm, 1, 16));
            const float mnew = fmaxf(m[i], rm);
            alpha[i] = __expf(m[i] - mnew);
            float rs = 0.f;
#pragma unroll
            for (int j = 0; j < 4; j++) {
                const float p = __expf(s[i][j] - mnew);
                s[i][j] = p; rs += p;
            }
            rs += __shfl_xor_sync(0xffffffffu, rs, 8, 16);
            rs += __shfl_xor_sync(0xffffffffu, rs, 4, 16);
            rs += __shfl_xor_sync(0xffffffffu, rs, 2, 16);
            rs += __shfl_xor_sync(0xffffffffu, rs, 1, 16);
            l[i] = l[i] * alpha[i] + rs;
            m[i] = mnew;
        }

        __syncthreads();
#pragma unroll
        for (int i = 0; i < 4; i++)
#pragma unroll
            for (int j = 0; j < 4; j++)
                b2[ty * 4 + i][tx * 4 + j] = s[i][j];
#pragma unroll
        for (int it = 0; it < 4; it++) {
            const int i = t + it * 256;
            const int r = i >> 4, c4 = (i & 15) << 2;
            *(float4*)&b1[r][c4] = *(const float4*)(Vb + (size_t)(k0 + r) * HD_ + c4);
        }
        __syncthreads();

#pragma unroll
        for (int i = 0; i < 4; i++)
#pragma unroll
            for (int j = 0; j < 4; j++) acc[i][j] *= alpha[i];

#pragma unroll 8
        for (int kc = 0; kc < 64; kc++) {
            float pv[4], vv[4];
#pragma unroll
            for (int i = 0; i < 4; i++) pv[i] = b2[ty * 4 + i][kc];
#pragma unroll
            for (int j = 0; j < 4; j++) vv[j] = b1[kc][tx * 4 + j];
#pragma unroll
            for (int i = 0; i < 4; i++)
#pragma unroll
                for (int j = 0; j < 4; j++)
                    acc[i][j] = fmaf(pv[i], vv[j], acc[i][j]);
        }
    }

    const int b = bh >> 4, h = bh & 15;
#pragma unroll
    for (int i = 0; i < 4; i++) {
        const float inv = 1.f / l[i];
        float4 v;
        v.x = acc[i][0] * inv; v.y = acc[i][1] * inv;
        v.z = acc[i][2] * inv; v.w = acc[i][3] * inv;
        const size_t row = (size_t)(b * S_ + q0 + ty * 4 + i);
        *(float4*)(ctx + row * DOUT + h * HD_ + tx * 4) = v;
    }
}

// ---------------------------------------------------------------------------
extern "C" void kernel_launch(void* const* d_in, const int* in_sizes, int n_in,
                              void* d_out, int out_size)
{
    (void)in_sizes; (void)n_in; (void)out_size;

    const float* x  = (const float*)d_in[0];
    const float* Wq = (const float*)d_in[1];
    const float* Wk = (const float*)d_in[2];
    const float* Wv = (const float*)d_in[3];
    const float* Wo = (const float*)d_in[4];
    const float* bo = (const float*)d_in[5];
    float* out = (float*)d_out;

    float *q, *k, *v, *c;
    __nv_bfloat16 *xh, *xl, *ch, *cl, *wh, *wl;
    cudaGetSymbolAddress((void**)&q, g_q);
    cudaGetSymbolAddress((void**)&k, g_k);
    cudaGetSymbolAddress((void**)&v, g_v);
    cudaGetSymbolAddress((void**)&c, g_ctx);
    cudaGetSymbolAddress((void**)&xh, g_xh);
    cudaGetSymbolAddress((void**)&xl, g_xl);
    cudaGetSymbolAddress((void**)&ch, g_ch);
    cudaGetSymbolAddress((void**)&cl, g_cl);
    cudaGetSymbolAddress((void**)&wh, g_wh);
    cudaGetSymbolAddress((void**)&wl, g_wl);

    cudaFuncSetAttribute(gemm_mma<true,  false>,
                         cudaFuncAttributeMaxDynamicSharedMemorySize, GEMM_SMEM);
    cudaFuncSetAttribute(gemm_mma<false, true>,
                         cudaFuncAttributeMaxDynamicSharedMemorySize, GEMM_SMEM);

    const size_t WSZ = (size_t)DOUT * DIN;
    split_kernel<<<(M_ * DIN / 4 + 255) / 256, 256>>>(x, xh, xl, M_ * DIN / 4);
    split_kernel<<<(int)(WSZ / 4 + 255) / 256, 256>>>(Wq, wh + 0 * WSZ, wl + 0 * WSZ, (int)(WSZ / 4));
    split_kernel<<<(int)(WSZ / 4 + 255) / 256, 256>>>(Wk, wh + 1 * WSZ, wl + 1 * WSZ, (int)(WSZ / 4));
    split_kernel<<<(int)(WSZ / 4 + 255) / 256, 256>>>(Wv, wh + 2 * WSZ, wl + 2 * WSZ, (int)(WSZ / 4));
    split_kernel<<<(int)(WSZ / 4 + 255) / 256, 256>>>(Wo, wh + 3 * WSZ, wl + 3 * WSZ, (int)(WSZ / 4));

    const dim3 ggrid(DOUT / 128, M_ / 128);   // (8, 64)
    gemm_mma<true,  false><<<ggrid, 256, GEMM_SMEM>>>(xh, xl, wh + 0 * WSZ, wl + 0 * WSZ, nullptr, q);
    gemm_mma<true,  false><<<ggrid, 256, GEMM_SMEM>>>(xh, xl, wh + 1 * WSZ, wl + 1 * WSZ, nullptr, k);
    gemm_mma<true,  false><<<ggrid, 256, GEMM_SMEM>>>(xh, xl, wh + 2 * WSZ, wl + 2 * WSZ, nullptr, v);

    attn_kernel<<<dim3(B_ * H_, S_ / 64), 256>>>(q, k, v, c);

    split_kernel<<<(M_ * DOUT / 4 + 255) / 256, 256>>>(c, ch, cl, M_ * DOUT / 4);
    gemm_mma<false, true><<<ggrid, 256, GEMM_SMEM>>>(ch, cl, wh + 3 * WSZ, wl + 3 * WSZ, bo, out);
}